// round 14
// baseline (speedup 1.0000x reference)
#include <cuda_runtime.h>

#define HID   256
#define BATCH 16
#define TLEN  1024
#define SEQ   256
#define RELAY_TPB 288       // 9 warps
#define NCHUNK 18           // 18*288 = 5184 >= 5151
#define RWARPS 9
#define PADT 33             // sh_ds step stride (32 used)
#define DPTS 18             // density points per block
#define DPAIRS 9            // f32x2 pairs used per feature row
#define DSTRIDE 12          // ull stride per feature row (96B, 16B-aligned)
#define DBLOCKS 288         // 2 CTAs/SM

// ---------------- scratch (static device globals; no allocation) ------------
__device__ float g_density[NCHUNK * RELAY_TPB];
__device__ float g_cb[BATCH * HID];
__device__ float g_dsum;
__device__ float g_scalars[3];                    // hs, ms, mo
__device__ float g_part[BATCH * NCHUNK * TLEN];   // 1.2 MB (block rows)

// ---------------- fast-math helpers ----------------------------------------
__device__ __forceinline__ float tanh_approx(float x) {
    float y; asm("tanh.approx.f32 %0, %1;" : "=f"(y) : "f"(x)); return y;
}
__device__ __forceinline__ unsigned long long pack2(float lo, float hi) {
    unsigned long long o;
    asm("mov.b64 %0, {%1, %2};" : "=l"(o)
        : "r"(__float_as_uint(lo)), "r"(__float_as_uint(hi)));
    return o;
}
__device__ __forceinline__ void unpack2(unsigned long long v, float& lo, float& hi) {
    unsigned int a, b;
    asm("mov.b64 {%0, %1}, %2;" : "=r"(a), "=r"(b) : "l"(v));
    lo = __uint_as_float(a); hi = __uint_as_float(b);
}
__device__ __forceinline__ unsigned long long fma2(unsigned long long a,
                                                   unsigned long long b,
                                                   unsigned long long c) {
    unsigned long long d;
    asm("fma.rn.f32x2 %0, %1, %2, %3;" : "=l"(d) : "l"(a), "l"(b), "l"(c));
    return d;
}

// ============================================================================
// K0: scalar prologue (keeps ncu capture slot on relay).
// ============================================================================
__global__ void scalar_kernel(const float* __restrict__ hsr,
                              const float* __restrict__ msr,
                              const float* __restrict__ mor)
{
    g_scalars[0] = 10.f / (1.f + expf(-hsr[0]));
    g_scalars[1] = 10.f / (1.f + expf(-msr[0]));
    g_scalars[2] = -10.f + 20.f / (1.f + expf(-mor[0]));
}

// ============================================================================
// K1: density MLP (batch-invariant), f32x2 FFMA2, 288 blocks x 18 points.
// ============================================================================
__global__ __launch_bounds__(256)
void density_kernel(const float* __restrict__ mesh,
                    const float* __restrict__ Win,
                    const float* __restrict__ bin,
                    const float* __restrict__ Wr,
                    const float* __restrict__ br,
                    const float* __restrict__ Wout,
                    const float* __restrict__ bout,
                    float* __restrict__ out_density,
                    float* __restrict__ out_mesh,
                    int NP)
{
    __shared__ __align__(16) unsigned long long hP[256 * DSTRIDE];  // 24,576 B
    __shared__ float smesh[2 * DPTS];

    const int j  = threadIdx.x;
    const int p0 = blockIdx.x * DPTS;

    if (j < 2 * DPTS) {
        int idx = p0 * 2 + j;
        smesh[j] = (idx < NP * 2) ? mesh[idx] : 0.f;
    }
    __syncthreads();

    float hreg[DPTS];
    {
        float w0 = Win[j], w1 = Win[HID + j], bj = bin[j];
        #pragma unroll
        for (int p = 0; p < DPTS; p++)
            hreg[p] = fmaxf(fmaf(smesh[2*p], w0, fmaf(smesh[2*p+1], w1, bj)), 0.f);
    }
    #pragma unroll
    for (int q = 0; q < DPAIRS; q++)
        hP[j * DSTRIDE + q] = pack2(hreg[2*q], hreg[2*q+1]);
    __syncthreads();

    for (int l = 0; l < 3; l++) {
        const float* __restrict__ W = Wr + l * HID * HID;
        unsigned long long acc[DPAIRS];
        #pragma unroll
        for (int q = 0; q < DPAIRS; q++) acc[q] = 0ull;

        #pragma unroll 4
        for (int k = 0; k < HID; k++) {
            float w = W[k * HID + j];
            unsigned long long wp = pack2(w, w);
            const unsigned long long* __restrict__ row = &hP[k * DSTRIDE];
            const ulonglong2* __restrict__ row2 =
                reinterpret_cast<const ulonglong2*>(row);
            #pragma unroll
            for (int qq = 0; qq < 4; qq++) {
                ulonglong2 hh = row2[qq];
                acc[2*qq]   = fma2(hh.x, wp, acc[2*qq]);
                acc[2*qq+1] = fma2(hh.y, wp, acc[2*qq+1]);
            }
            acc[8] = fma2(row[8], wp, acc[8]);
        }
        float bb = br[l * HID + j];
        __syncthreads();
        #pragma unroll
        for (int q = 0; q < DPAIRS; q++) {
            float lo, hi; unpack2(acc[q], lo, hi);
            hreg[2*q]   += fmaxf(lo + bb, 0.f);
            hreg[2*q+1] += fmaxf(hi + bb, 0.f);
            hP[j * DSTRIDE + q] = pack2(hreg[2*q], hreg[2*q+1]);
        }
        __syncthreads();
    }

    const float* __restrict__ hPf = reinterpret_cast<const float*>(hP);
    const int warp = j >> 5, lane = j & 31;
    float wv[8];
    #pragma unroll
    for (int i = 0; i < 8; i++) wv[i] = Wout[lane + i * 32];
    float b0 = bout[0];

    #pragma unroll
    for (int q = 0; q < 3; q++) {
        int p = warp * 3 + q;
        if (p >= DPTS) break;
        float d = 0.f;
        #pragma unroll
        for (int i = 0; i < 8; i++)
            d = fmaf(hPf[(lane + i * 32) * (2 * DSTRIDE) + p], wv[i], d);
        #pragma unroll
        for (int o = 16; o > 0; o >>= 1)
            d += __shfl_xor_sync(0xffffffffu, d, o);
        if (lane == 0 && p0 + p < NP) {
            float dens = 1.f / (1.f + expf(-(d + b0)));
            g_density[p0 + p] = dens;
            #pragma unroll
            for (int b = 0; b < BATCH; b++)
                out_density[b * NP + p0 + p] = dens;
        }
    }

    if (j < 2 * DPTS) {
        int idx = p0 * 2 + j;
        if (idx < NP * 2) {
            float v = smesh[j];
            #pragma unroll
            for (int b = 0; b < BATCH; b++)
                out_mesh[b * NP * 2 + idx] = v;
        }
    }
}

// ============================================================================
// K2: encoder context -> cb[b] = ctx@Wc + bm ; block BATCH computes dsum.
// ============================================================================
__global__ void encoder_kernel(const float* __restrict__ enc_in,
                               const float* __restrict__ mask,
                               const float* __restrict__ Ws,
                               const float* __restrict__ bs,
                               const float* __restrict__ Wc,
                               const float* __restrict__ bm,
                               int NP)
{
    const int b = blockIdx.x;
    const int j = threadIdx.x;

    if (b == BATCH) {
        __shared__ float red[256];
        float s = 0.f;
        for (int i = j; i < NP; i += 256) s += g_density[i];
        red[j] = s;
        __syncthreads();
        for (int o = 128; o > 0; o >>= 1) {
            if (j < o) red[j] += red[j + o];
            __syncthreads();
        }
        if (j == 0) g_dsum = red[0];
        return;
    }

    __shared__ float se[SEQ * 2];
    __shared__ float sm[SEQ];
    __shared__ float sctx[HID];

    for (int i = j; i < SEQ * 2; i += 256) se[i] = enc_in[b * SEQ * 2 + i];
    sm[j] = mask[b * SEQ + j];
    __syncthreads();

    float w0 = Ws[j], w1 = Ws[HID + j], bj = bs[j];
    float acc = 0.f, msum = 0.f;
    for (int s = 0; s < SEQ; s++) {
        float mk = sm[s];
        float v  = fmaf(se[2*s], w0, fmaf(se[2*s+1], w1, bj));
        acc  = fmaf(mk, fmaxf(v, 0.f), acc);
        msum += mk;
    }
    sctx[j] = acc / fmaxf(msum, 1.f);
    __syncthreads();

    float cb = bm[j];
    for (int k = 0; k < HID; k++)
        cb = fmaf(sctx[k], Wc[k * HID + j], cb);
    g_cb[b * HID + j] = cb;
}

// ============================================================================
// K3: relay scan — the ACTUAL 78.2us configuration (R6 design, profiled in
//   round 7): 288 threads / 9 warps, 1 point per lane.  Per step: 2x
//   tanh.approx + relay algebra + ONE STS (no shuffles).  Every 32 steps a
//   transposed two-stage block reduction writes 32 block partials.
// ============================================================================
__global__ __launch_bounds__(RELAY_TPB)
void relay_kernel(const float* __restrict__ mesh,
                  const float* __restrict__ dec,
                  const float* __restrict__ Wm,
                  const float* __restrict__ Wo,
                  const float* __restrict__ bo,
                  float* __restrict__ out_init,
                  int NP)
{
    __shared__ float sh_h[TLEN];                   //  4,096 B (pre-scaled x500)
    __shared__ float sh_ds[RELAY_TPB * PADT];      // 38,016 B
    __shared__ float sh_red[32 * (RWARPS + 1)];    //  1,280 B
    __shared__ float s_cb[HID], s_wm0[HID], s_wm1[HID], s_wm2[HID], s_wo[HID];

    const int tid   = threadIdx.x;
    const int chunk = blockIdx.x;
    const int b     = blockIdx.y;
    const int p     = chunk * RELAY_TPB + tid;
    const bool valid = (p < NP);

    const float SC = 500.0f;   // 1/(2*TEMP)

    for (int i = tid; i < TLEN; i += RELAY_TPB)
        sh_h[i] = dec[b * TLEN + i] * SC;
    if (tid < HID) {
        s_cb[tid]  = g_cb[b * HID + tid];
        s_wm0[tid] = Wm[tid];
        s_wm1[tid] = Wm[HID + tid];
        s_wm2[tid] = Wm[2 * HID + tid];
        s_wo[tid]  = Wo[tid];
    }
    __syncthreads();

    float beta  = valid ? mesh[2*p]     : 0.f;
    float alpha = valid ? mesh[2*p + 1] : 0.f;
    float dens  = valid ? g_density[p]  : 0.f;

    // ---- fused initial_states (precise) ----
    float acc = 0.f;
    #pragma unroll 8
    for (int jj = 0; jj < HID; jj++) {
        float pre = fmaf(beta, s_wm0[jj],
                    fmaf(alpha, s_wm1[jj],
                    fmaf(dens,  s_wm2[jj], s_cb[jj])));
        acc = fmaf(fmaxf(pre, 0.f), s_wo[jj], acc);
    }
    float s = tanhf(acc + bo[0]);
    if (valid) out_init[b * NP + p] = s;
    if (!valid) s = 0.f;

    const float a500 = alpha * SC;
    const float b500 = beta  * SC;
    float* __restrict__ my_ds = sh_ds + tid * PADT;
    const int l2 = tid & 31, w = tid >> 5;
    const float* __restrict__ col_base = sh_ds + (w * 32) * PADT + l2;
    float* __restrict__ gdst = g_part + (b * NCHUNK + chunk) * TLEN;

    for (int tile = 0; tile < TLEN / 32; tile++) {
        const float* __restrict__ ht_base = sh_h + tile * 32;
        #pragma unroll
        for (int tl = 0; tl < 32; tl++) {
            float ht = ht_base[tl];
            float tu = tanh_approx(ht - a500);      // 2*w_up - 1
            float td = tanh_approx(b500 - ht);      // 2*w_dn - 1
            float u = 1.f - s, v = 1.f + s;
            s = 0.5f * fmaf(tu, u, v);
            float a2 = s - 1.f, b2 = s + 1.f;
            s = 0.5f * fmaf(-td, b2, a2);
            my_ds[tl] = dens * s;
        }
        __syncthreads();

        // stage 2: thread (w,l2) sums 32 rows at column l2
        {
            float sum = 0.f;
            #pragma unroll
            for (int r = 0; r < 32; r++)
                sum += col_base[r * PADT];
            sh_red[l2 * (RWARPS + 1) + w] = sum;
        }
        __syncthreads();

        // stage 3: warp 0 combines the 9 row-group partials -> global
        if (tid < 32) {
            float tot = 0.f;
            #pragma unroll
            for (int ww = 0; ww < RWARPS; ww++)
                tot += sh_red[tid * (RWARPS + 1) + ww];
            gdst[tile * 32 + tid] = tot;
        }
        // no extra barrier: next tile writes sh_ds (read done before bar2);
        // next sh_red write happens after next bar1, past warp0's reads.
    }
}

// ============================================================================
// K4: reduce NCHUNK block rows -> m, then b_out.
// ============================================================================
__global__ void finalize_kernel(const float* __restrict__ dec,
                                float* __restrict__ out_b,
                                float* __restrict__ out_m)
{
    const int idx = blockIdx.x * 256 + threadIdx.x;
    const int b = idx >> 10;
    const int t = idx & (TLEN - 1);

    const float* __restrict__ base = g_part + b * NCHUNK * TLEN + t;
    float msum = 0.f;
    #pragma unroll
    for (int w = 0; w < NCHUNK; w++)
        msum += base[w * TLEN];

    float m  = msum / g_dsum;
    float h  = dec[idx];
    out_m[idx] = m;
    out_b[idx] = fmaf(g_scalars[0], h, fmaf(g_scalars[1], m, g_scalars[2]));
}

// ============================================================================
// launch
// ============================================================================
extern "C" void kernel_launch(void* const* d_in, const int* in_sizes, int n_in,
                              void* d_out, int out_size)
{
    const float* enc_in = (const float*)d_in[0];
    const float* dec    = (const float*)d_in[1];
    const float* mask   = (const float*)d_in[2];
    const float* mesh   = (const float*)d_in[3];
    const float* Win    = (const float*)d_in[4];
    const float* bin    = (const float*)d_in[5];
    const float* Wr     = (const float*)d_in[6];
    const float* br     = (const float*)d_in[7];
    const float* Wout   = (const float*)d_in[8];
    const float* bout   = (const float*)d_in[9];
    const float* Ws     = (const float*)d_in[10];
    const float* bs     = (const float*)d_in[11];
    const float* Wm     = (const float*)d_in[12];
    const float* Wc     = (const float*)d_in[13];
    const float* bm     = (const float*)d_in[14];
    const float* Wo     = (const float*)d_in[15];
    const float* bo     = (const float*)d_in[16];
    const float* hsr    = (const float*)d_in[17];
    const float* msr    = (const float*)d_in[18];
    const float* mor    = (const float*)d_in[19];

    const int NP = in_sizes[3] / 2;                 // 5151

    float* O        = (float*)d_out;
    float* out_b    = O;                            // (16,1024)
    float* out_dens = O + BATCH * TLEN;             // (16,NP)
    float* out_m    = out_dens + BATCH * NP;        // (16,1024)
    float* out_init = out_m + BATCH * TLEN;         // (16,NP)
    float* out_mesh = out_init + BATCH * NP;        // (16,NP,2)

    scalar_kernel<<<1, 1>>>(hsr, msr, mor);
    density_kernel<<<DBLOCKS, 256>>>(mesh, Win, bin, Wr, br, Wout, bout,
                                     out_dens, out_mesh, NP);
    encoder_kernel<<<BATCH + 1, 256>>>(enc_in, mask, Ws, bs, Wc, bm, NP);
    relay_kernel<<<dim3(NCHUNK, BATCH), RELAY_TPB>>>(mesh, dec, Wm, Wo, bo,
                                                     out_init, NP);
    finalize_kernel<<<(BATCH * TLEN) / 256, 256>>>(dec, out_b, out_m);
}

// round 15
// speedup vs baseline: 1.5958x; 1.5958x over previous
#include <cuda_runtime.h>

#define HID   256
#define BATCH 16
#define TLEN  1024
#define SEQ   256
#define RELAY_TPB 288       // 9 warps
#define NCHUNK 18           // 18*288 = 5184 >= 5151
#define RWARPS 9
#define PADT 33             // sh_ds step stride (32 used)
#define DPTS 18             // density points per block
#define DPAIRS 9            // f32x2 pairs used per feature row
#define DSTRIDE 12          // ull stride per feature row (96B, 16B-aligned)
#define DBLOCKS 288         // 2 CTAs/SM

// ---------------- scratch (static device globals; no allocation) ------------
__device__ float g_density[NCHUNK * RELAY_TPB];
__device__ float g_cb[BATCH * HID];
__device__ float g_dsum;
__device__ float g_scalars[3];                    // hs, ms, mo
__device__ float g_part[BATCH * NCHUNK * TLEN];   // 1.2 MB (block rows)

// ---------------- fast-math helpers ----------------------------------------
__device__ __forceinline__ float tanh_approx(float x) {
    float y; asm("tanh.approx.f32 %0, %1;" : "=f"(y) : "f"(x)); return y;
}
__device__ __forceinline__ unsigned long long pack2(float lo, float hi) {
    unsigned long long o;
    asm("mov.b64 %0, {%1, %2};" : "=l"(o)
        : "r"(__float_as_uint(lo)), "r"(__float_as_uint(hi)));
    return o;
}
__device__ __forceinline__ void unpack2(unsigned long long v, float& lo, float& hi) {
    unsigned int a, b;
    asm("mov.b64 {%0, %1}, %2;" : "=r"(a), "=r"(b) : "l"(v));
    lo = __uint_as_float(a); hi = __uint_as_float(b);
}
__device__ __forceinline__ unsigned long long fma2(unsigned long long a,
                                                   unsigned long long b,
                                                   unsigned long long c) {
    unsigned long long d;
    asm("fma.rn.f32x2 %0, %1, %2, %3;" : "=l"(d) : "l"(a), "l"(b), "l"(c));
    return d;
}

// ============================================================================
// K0: scalar prologue (keeps ncu capture slot on relay).
// ============================================================================
__global__ void scalar_kernel(const float* __restrict__ hsr,
                              const float* __restrict__ msr,
                              const float* __restrict__ mor)
{
    g_scalars[0] = 10.f / (1.f + expf(-hsr[0]));
    g_scalars[1] = 10.f / (1.f + expf(-msr[0]));
    g_scalars[2] = -10.f + 20.f / (1.f + expf(-mor[0]));
}

// ============================================================================
// K1: density MLP (batch-invariant), f32x2 FFMA2, 288 blocks x 18 points.
// ============================================================================
__global__ __launch_bounds__(256)
void density_kernel(const float* __restrict__ mesh,
                    const float* __restrict__ Win,
                    const float* __restrict__ bin,
                    const float* __restrict__ Wr,
                    const float* __restrict__ br,
                    const float* __restrict__ Wout,
                    const float* __restrict__ bout,
                    float* __restrict__ out_density,
                    float* __restrict__ out_mesh,
                    int NP)
{
    __shared__ __align__(16) unsigned long long hP[256 * DSTRIDE];  // 24,576 B
    __shared__ float smesh[2 * DPTS];

    const int j  = threadIdx.x;
    const int p0 = blockIdx.x * DPTS;

    if (j < 2 * DPTS) {
        int idx = p0 * 2 + j;
        smesh[j] = (idx < NP * 2) ? mesh[idx] : 0.f;
    }
    __syncthreads();

    float hreg[DPTS];
    {
        float w0 = Win[j], w1 = Win[HID + j], bj = bin[j];
        #pragma unroll
        for (int p = 0; p < DPTS; p++)
            hreg[p] = fmaxf(fmaf(smesh[2*p], w0, fmaf(smesh[2*p+1], w1, bj)), 0.f);
    }
    #pragma unroll
    for (int q = 0; q < DPAIRS; q++)
        hP[j * DSTRIDE + q] = pack2(hreg[2*q], hreg[2*q+1]);
    __syncthreads();

    for (int l = 0; l < 3; l++) {
        const float* __restrict__ W = Wr + l * HID * HID;
        unsigned long long acc[DPAIRS];
        #pragma unroll
        for (int q = 0; q < DPAIRS; q++) acc[q] = 0ull;

        #pragma unroll 4
        for (int k = 0; k < HID; k++) {
            float w = W[k * HID + j];
            unsigned long long wp = pack2(w, w);
            const unsigned long long* __restrict__ row = &hP[k * DSTRIDE];
            const ulonglong2* __restrict__ row2 =
                reinterpret_cast<const ulonglong2*>(row);
            #pragma unroll
            for (int qq = 0; qq < 4; qq++) {
                ulonglong2 hh = row2[qq];
                acc[2*qq]   = fma2(hh.x, wp, acc[2*qq]);
                acc[2*qq+1] = fma2(hh.y, wp, acc[2*qq+1]);
            }
            acc[8] = fma2(row[8], wp, acc[8]);
        }
        float bb = br[l * HID + j];
        __syncthreads();
        #pragma unroll
        for (int q = 0; q < DPAIRS; q++) {
            float lo, hi; unpack2(acc[q], lo, hi);
            hreg[2*q]   += fmaxf(lo + bb, 0.f);
            hreg[2*q+1] += fmaxf(hi + bb, 0.f);
            hP[j * DSTRIDE + q] = pack2(hreg[2*q], hreg[2*q+1]);
        }
        __syncthreads();
    }

    const float* __restrict__ hPf = reinterpret_cast<const float*>(hP);
    const int warp = j >> 5, lane = j & 31;
    float wv[8];
    #pragma unroll
    for (int i = 0; i < 8; i++) wv[i] = Wout[lane + i * 32];
    float b0 = bout[0];

    #pragma unroll
    for (int q = 0; q < 3; q++) {
        int p = warp * 3 + q;
        if (p >= DPTS) break;
        float d = 0.f;
        #pragma unroll
        for (int i = 0; i < 8; i++)
            d = fmaf(hPf[(lane + i * 32) * (2 * DSTRIDE) + p], wv[i], d);
        #pragma unroll
        for (int o = 16; o > 0; o >>= 1)
            d += __shfl_xor_sync(0xffffffffu, d, o);
        if (lane == 0 && p0 + p < NP) {
            float dens = 1.f / (1.f + expf(-(d + b0)));
            g_density[p0 + p] = dens;
            #pragma unroll
            for (int b = 0; b < BATCH; b++)
                out_density[b * NP + p0 + p] = dens;
        }
    }

    if (j < 2 * DPTS) {
        int idx = p0 * 2 + j;
        if (idx < NP * 2) {
            float v = smesh[j];
            #pragma unroll
            for (int b = 0; b < BATCH; b++)
                out_mesh[b * NP * 2 + idx] = v;
        }
    }
}

// ============================================================================
// K2: encoder context -> cb[b] = ctx@Wc + bm ; block BATCH computes dsum.
// ============================================================================
__global__ void encoder_kernel(const float* __restrict__ enc_in,
                               const float* __restrict__ mask,
                               const float* __restrict__ Ws,
                               const float* __restrict__ bs,
                               const float* __restrict__ Wc,
                               const float* __restrict__ bm,
                               int NP)
{
    const int b = blockIdx.x;
    const int j = threadIdx.x;

    if (b == BATCH) {
        __shared__ float red[256];
        float s = 0.f;
        for (int i = j; i < NP; i += 256) s += g_density[i];
        red[j] = s;
        __syncthreads();
        for (int o = 128; o > 0; o >>= 1) {
            if (j < o) red[j] += red[j + o];
            __syncthreads();
        }
        if (j == 0) g_dsum = red[0];
        return;
    }

    __shared__ float se[SEQ * 2];
    __shared__ float sm[SEQ];
    __shared__ float sctx[HID];

    for (int i = j; i < SEQ * 2; i += 256) se[i] = enc_in[b * SEQ * 2 + i];
    sm[j] = mask[b * SEQ + j];
    __syncthreads();

    float w0 = Ws[j], w1 = Ws[HID + j], bj = bs[j];
    float acc = 0.f, msum = 0.f;
    for (int s = 0; s < SEQ; s++) {
        float mk = sm[s];
        float v  = fmaf(se[2*s], w0, fmaf(se[2*s+1], w1, bj));
        acc  = fmaf(mk, fmaxf(v, 0.f), acc);
        msum += mk;
    }
    sctx[j] = acc / fmaxf(msum, 1.f);
    __syncthreads();

    float cb = bm[j];
    for (int k = 0; k < HID; k++)
        cb = fmaf(sctx[k], Wc[k * HID + j], cb);
    g_cb[b * HID + j] = cb;
}

// ============================================================================
// K3: relay scan — best-known configuration (78.2us at normal clocks):
//   288 threads / 9 warps, 1 point per lane.  Per step: 2x tanh.approx +
//   relay algebra + ONE STS (no shuffles).  Every 32 steps a transposed
//   two-stage block reduction writes 32 block partials.
// ============================================================================
__global__ __launch_bounds__(RELAY_TPB)
void relay_kernel(const float* __restrict__ mesh,
                  const float* __restrict__ dec,
                  const float* __restrict__ Wm,
                  const float* __restrict__ Wo,
                  const float* __restrict__ bo,
                  float* __restrict__ out_init,
                  int NP)
{
    __shared__ float sh_h[TLEN];                   //  4,096 B (pre-scaled x500)
    __shared__ float sh_ds[RELAY_TPB * PADT];      // 38,016 B
    __shared__ float sh_red[32 * (RWARPS + 1)];    //  1,280 B
    __shared__ float s_cb[HID], s_wm0[HID], s_wm1[HID], s_wm2[HID], s_wo[HID];

    const int tid   = threadIdx.x;
    const int chunk = blockIdx.x;
    const int b     = blockIdx.y;
    const int p     = chunk * RELAY_TPB + tid;
    const bool valid = (p < NP);

    const float SC = 500.0f;   // 1/(2*TEMP)

    for (int i = tid; i < TLEN; i += RELAY_TPB)
        sh_h[i] = dec[b * TLEN + i] * SC;
    if (tid < HID) {
        s_cb[tid]  = g_cb[b * HID + tid];
        s_wm0[tid] = Wm[tid];
        s_wm1[tid] = Wm[HID + tid];
        s_wm2[tid] = Wm[2 * HID + tid];
        s_wo[tid]  = Wo[tid];
    }
    __syncthreads();

    float beta  = valid ? mesh[2*p]     : 0.f;
    float alpha = valid ? mesh[2*p + 1] : 0.f;
    float dens  = valid ? g_density[p]  : 0.f;

    // ---- fused initial_states (precise) ----
    float acc = 0.f;
    #pragma unroll 8
    for (int jj = 0; jj < HID; jj++) {
        float pre = fmaf(beta, s_wm0[jj],
                    fmaf(alpha, s_wm1[jj],
                    fmaf(dens,  s_wm2[jj], s_cb[jj])));
        acc = fmaf(fmaxf(pre, 0.f), s_wo[jj], acc);
    }
    float s = tanhf(acc + bo[0]);
    if (valid) out_init[b * NP + p] = s;
    if (!valid) s = 0.f;

    const float a500 = alpha * SC;
    const float b500 = beta  * SC;
    float* __restrict__ my_ds = sh_ds + tid * PADT;
    const int l2 = tid & 31, w = tid >> 5;
    const float* __restrict__ col_base = sh_ds + (w * 32) * PADT + l2;
    float* __restrict__ gdst = g_part + (b * NCHUNK + chunk) * TLEN;

    for (int tile = 0; tile < TLEN / 32; tile++) {
        const float* __restrict__ ht_base = sh_h + tile * 32;
        #pragma unroll
        for (int tl = 0; tl < 32; tl++) {
            float ht = ht_base[tl];
            float tu = tanh_approx(ht - a500);      // 2*w_up - 1
            float td = tanh_approx(b500 - ht);      // 2*w_dn - 1
            float u = 1.f - s, v = 1.f + s;
            s = 0.5f * fmaf(tu, u, v);
            float a2 = s - 1.f, b2 = s + 1.f;
            s = 0.5f * fmaf(-td, b2, a2);
            my_ds[tl] = dens * s;
        }
        __syncthreads();

        // stage 2: thread (w,l2) sums 32 rows at column l2
        {
            float sum = 0.f;
            #pragma unroll
            for (int r = 0; r < 32; r++)
                sum += col_base[r * PADT];
            sh_red[l2 * (RWARPS + 1) + w] = sum;
        }
        __syncthreads();

        // stage 3: warp 0 combines the 9 row-group partials -> global
        if (tid < 32) {
            float tot = 0.f;
            #pragma unroll
            for (int ww = 0; ww < RWARPS; ww++)
                tot += sh_red[tid * (RWARPS + 1) + ww];
            gdst[tile * 32 + tid] = tot;
        }
        // no extra barrier: next tile writes sh_ds (read done before bar2);
        // next sh_red write happens after next bar1, past warp0's reads.
    }
}

// ============================================================================
// K4: reduce NCHUNK block rows -> m, then b_out.
// ============================================================================
__global__ void finalize_kernel(const float* __restrict__ dec,
                                float* __restrict__ out_b,
                                float* __restrict__ out_m)
{
    const int idx = blockIdx.x * 256 + threadIdx.x;
    const int b = idx >> 10;
    const int t = idx & (TLEN - 1);

    const float* __restrict__ base = g_part + b * NCHUNK * TLEN + t;
    float msum = 0.f;
    #pragma unroll
    for (int w = 0; w < NCHUNK; w++)
        msum += base[w * TLEN];

    float m  = msum / g_dsum;
    float h  = dec[idx];
    out_m[idx] = m;
    out_b[idx] = fmaf(g_scalars[0], h, fmaf(g_scalars[1], m, g_scalars[2]));
}

// ============================================================================
// launch
// ============================================================================
extern "C" void kernel_launch(void* const* d_in, const int* in_sizes, int n_in,
                              void* d_out, int out_size)
{
    const float* enc_in = (const float*)d_in[0];
    const float* dec    = (const float*)d_in[1];
    const float* mask   = (const float*)d_in[2];
    const float* mesh   = (const float*)d_in[3];
    const float* Win    = (const float*)d_in[4];
    const float* bin    = (const float*)d_in[5];
    const float* Wr     = (const float*)d_in[6];
    const float* br     = (const float*)d_in[7];
    const float* Wout   = (const float*)d_in[8];
    const float* bout   = (const float*)d_in[9];
    const float* Ws     = (const float*)d_in[10];
    const float* bs     = (const float*)d_in[11];
    const float* Wm     = (const float*)d_in[12];
    const float* Wc     = (const float*)d_in[13];
    const float* bm     = (const float*)d_in[14];
    const float* Wo     = (const float*)d_in[15];
    const float* bo     = (const float*)d_in[16];
    const float* hsr    = (const float*)d_in[17];
    const float* msr    = (const float*)d_in[18];
    const float* mor    = (const float*)d_in[19];

    const int NP = in_sizes[3] / 2;                 // 5151

    float* O        = (float*)d_out;
    float* out_b    = O;                            // (16,1024)
    float* out_dens = O + BATCH * TLEN;             // (16,NP)
    float* out_m    = out_dens + BATCH * NP;        // (16,1024)
    float* out_init = out_m + BATCH * TLEN;         // (16,NP)
    float* out_mesh = out_init + BATCH * NP;        // (16,NP,2)

    scalar_kernel<<<1, 1>>>(hsr, msr, mor);
    density_kernel<<<DBLOCKS, 256>>>(mesh, Win, bin, Wr, br, Wout, bout,
                                     out_dens, out_mesh, NP);
    encoder_kernel<<<BATCH + 1, 256>>>(enc_in, mask, Ws, bs, Wc, bm, NP);
    relay_kernel<<<dim3(NCHUNK, BATCH), RELAY_TPB>>>(mesh, dec, Wm, Wo, bo,
                                                     out_init, NP);
    finalize_kernel<<<(BATCH * TLEN) / 256, 256>>>(dec, out_b, out_m);
}